// round 11
// baseline (speedup 1.0000x reference)
#include <cuda_runtime.h>
#include <cstdint>

#define HH 512
#define WW 512
#define WORDS 16
#define SLAB 32
#define HALO 3
#define NLOAD (SLAB + HALO)            // 35 rows
#define NTH 128
#define NWARPS 4
#define NOFF 12
#define SLABS (HH / SLAB)              // 16
#define MAXB 128
#define ROWB (WW * 4)                  // 2048 bytes per row
#define BITS_WORDS (NLOAD * WORDS + WORDS)   // 576 (incl. guard row)

// zero-initialized; every use paired with a reset -> deterministic graph replays
__device__ int g_cnt[MAXB * NOFF * 2];     // [image][offset]{diff, n11}
__device__ unsigned g_arrive[MAXB];

__device__ __forceinline__ void mbar_init(unsigned a, unsigned cnt) {
    asm volatile("mbarrier.init.shared.b64 [%0], %1;" :: "r"(a), "r"(cnt) : "memory");
}
__device__ __forceinline__ void mbar_expect_tx(unsigned a, unsigned bytes) {
    asm volatile("mbarrier.arrive.expect_tx.shared.b64 _, [%0], %1;"
                 :: "r"(a), "r"(bytes) : "memory");
}
__device__ __forceinline__ void bulk_g2s(unsigned dst, const float* src,
                                         unsigned bytes, unsigned mbar) {
    asm volatile("cp.async.bulk.shared::cluster.global.mbarrier::complete_tx::bytes "
                 "[%0], [%1], %2, [%3];"
                 :: "r"(dst), "l"(src), "r"(bytes), "r"(mbar) : "memory");
}
__device__ __forceinline__ void mbar_wait(unsigned a, unsigned parity) {
    asm volatile(
        "{\n\t"
        ".reg .pred P1;\n\t"
        "WAIT_LOOP_%=:\n\t"
        "mbarrier.try_wait.parity.shared.b64 P1, [%0], %1;\n\t"
        "@P1 bra.uni WAIT_DONE_%=;\n\t"
        "bra.uni WAIT_LOOP_%=;\n\t"
        "WAIT_DONE_%=:\n\t"
        "}"
        :: "r"(a), "r"(parity) : "memory");
}

// evaluate all 12 offsets for bit-word (r, w)
__device__ __forceinline__ void eval12(const unsigned* __restrict__ bits,
                                       int r, int w,
                                       const int* __restrict__ rl,
                                       unsigned* __restrict__ acc)
{
    constexpr int RS[NOFF] = {0, 1, 1, 1, 0, 2, 2, 2, 0, 3, 3, 3};
    constexpr int CS[NOFF] = {1, 1, 0, -1, 2, 2, 0, -2, 3, 3, 0, -3};
    const bool firstw = (w == 0);
    const bool lastw  = (w == WORDS - 1);
    const int i = r * WORDS + w;
    const unsigned A = bits[i];

    #pragma unroll
    for (int o = 0; o < NOFF; ++o) {
        const int R = RS[o];
        const int C = CS[o];
        const int bi = i + R * WORDS;
        unsigned B;
        if (C > 0)       B = __funnelshift_r(bits[bi], bits[bi + 1], C);
        else if (C < 0)  B = __funnelshift_l(bits[bi - 1], bits[bi], -C);
        else             B = bits[bi];

        unsigned m = 0xffffffffu;
        if (C > 0 && lastw)  m = 0xffffffffu >> C;
        if (C < 0 && firstw) m = 0xffffffffu << (-C);
        if (r >= rl[R]) m = 0u;              // last-slab row clip

        acc[o] += (unsigned)(__popc((A ^ B) & m) << 16)
                |  (unsigned)__popc((A & B) & m);
    }
}

extern __shared__ unsigned char dynsmem[];

__global__ __launch_bounds__(NTH, 3)
void glcm_bulk(const float* __restrict__ in, float* __restrict__ out)
{
    constexpr int RS[NOFF] = {0, 1, 1, 1, 0, 2, 2, 2, 0, 3, 3, 3};
    constexpr int CS[NOFF] = {1, 1, 0, -1, 2, 2, 0, -2, 3, 3, 0, -3};

    float*    sbuf = reinterpret_cast<float*>(dynsmem);            // 35 rows floats
    unsigned* bits = reinterpret_cast<unsigned*>(dynsmem + NLOAD * ROWB);
    __shared__ unsigned long long s_mbar;
    __shared__ int s_diff[NOFF];
    __shared__ int s_n11[NOFF];
    __shared__ int s_last;

    const int tid  = threadIdx.x;
    const int lane = tid & 31;
    const int warp = tid >> 5;
    const int r0   = blockIdx.x * SLAB;
    const int b    = blockIdx.y;
    const float* img = in + ((size_t)b * HH + r0) * WW;

    const int nload = min(NLOAD, HH - r0);   // 35, or 32 for last slab
    const unsigned mb = (unsigned)__cvta_generic_to_shared(&s_mbar);

    if (tid < NOFF) { s_diff[tid] = 0; s_n11[tid] = 0; }
    if (tid == 0) mbar_init(mb, 1u);
    __syncthreads();                          // mbar init visible block-wide

    // ---- ONE bulk TMA for the whole slab (+halo); queued immediately -------
    if (tid == 0) {
        const unsigned bytes = (unsigned)nload * ROWB;
        mbar_expect_tx(mb, bytes);
        bulk_g2s((unsigned)__cvta_generic_to_shared(sbuf), img, bytes, mb);
    }
    mbar_wait(mb, 0u);                        // all threads; single wait

    // ---- pack: SMEM floats -> ballot -> bit-plane ---------------------------
    for (int r = warp; r < nload; r += NWARPS) {
        const float* rp = sbuf + r * WW;
        unsigned b4[4];
        #pragma unroll
        for (int w = 0; w < WORDS; ++w) {
            float v = rp[w * 32 + lane];
            b4[w & 3] = __ballot_sync(0xffffffffu, v > 0.0f);
            if ((w & 3) == 3 && lane == 0)
                *reinterpret_cast<uint4*>(&bits[r * WORDS + (w - 3)])
                    = make_uint4(b4[0], b4[1], b4[2], b4[3]);
        }
    }
    __syncthreads();                          // the only block barrier

    // ---- count: 32 a-rows x 16 words, all 12 offsets ------------------------
    int rl[4];
    #pragma unroll
    for (int R = 0; R < 4; ++R) rl[R] = min(SLAB, HH - R - r0);

    unsigned acc[NOFF];
    #pragma unroll
    for (int o = 0; o < NOFF; ++o) acc[o] = 0;

    #pragma unroll
    for (int e = tid; e < SLAB * WORDS; e += NTH)
        eval12(bits, e >> 4, e & 15, rl, acc);

    // ---- reduce: warp -> block -> global -------------------------------------
    #pragma unroll
    for (int o = 0; o < NOFF; ++o) {
        unsigned v = __reduce_add_sync(0xffffffffu, acc[o]);
        if (lane == 0) {
            atomicAdd(&s_diff[o], (int)(v >> 16));
            atomicAdd(&s_n11[o],  (int)(v & 0xffffu));
        }
    }
    __syncthreads();

    if (tid < NOFF) {
        atomicAdd(&g_cnt[(b * NOFF + tid) * 2 + 0], s_diff[tid]);
        atomicAdd(&g_cnt[(b * NOFF + tid) * 2 + 1], s_n11[tid]);
    }

    // ---- last slab-block of this image finalizes -----------------------------
    if (tid == 0) {
        __threadfence();
        unsigned t = atomicAdd(&g_arrive[b], 1u);
        s_last = (t == SLABS - 1);
    }
    __syncthreads();

    if (s_last && tid < NOFF) {
        const int idx  = b * NOFF + tid;
        const int diff = atomicExch(&g_cnt[idx * 2 + 0], 0);   // read + reset
        const int n11  = atomicExch(&g_cnt[idx * 2 + 1], 0);
        if (tid == 0) atomicExch(&g_arrive[b], 0u);

        const int R  = RS[tid];
        const int Ca = CS[tid] < 0 ? -CS[tid] : CS[tid];
        const int N  = (HH - R) * (WW - Ca);
        const int n00 = N - n11 - diff;

        const float inv = 1.0f / (float)(2 * N - 4 * n00);
        float* o = out + (size_t)b * (NOFF * 4) + tid * 4;
        o[0] = (float)(4 * n00) * inv;
        const float v1 = (float)(2 * diff - 4 * n00) * inv;
        o[1] = v1;
        o[2] = v1;
        o[3] = (float)(2 * (N - 2 * diff)) * inv;
    }
}

extern "C" void kernel_launch(void* const* d_in, const int* in_sizes, int n_in,
                              void* d_out, int out_size)
{
    (void)n_in; (void)out_size;
    const int batch = in_sizes[0] / (HH * WW);         // 128
    const int smem = NLOAD * ROWB + BITS_WORDS * 4;    // 71680 + 2304 = 73984 B
    cudaFuncSetAttribute(glcm_bulk, cudaFuncAttributeMaxDynamicSharedMemorySize, smem);
    dim3 grid(SLABS, batch);                           // 16 x 128 = 2048 blocks
    glcm_bulk<<<grid, NTH, smem>>>((const float*)d_in[0], (float*)d_out);
}